// round 1
// baseline (speedup 1.0000x reference)
#include <cuda_runtime.h>

#define SEQ   512
#define DIM   512
#define HEADS 8
#define DH    64
#define DR    16
#define HD    128

// ---------------- device scratch (no cudaMalloc allowed) ----------------
__device__ float g_xn  [SEQ*DIM];          // layernorm output
__device__ float g_qkv [SEQ*3*DIM];        // q1|k1|v1 (cols 0..511 | 512..1023 | 1024..1535)
__device__ float g_aq  [SEQ*HD];
__device__ float g_ak  [SEQ*HD];
__device__ float g_av  [SEQ*HD];
__device__ float g_dots[HEADS*SEQ*SEQ];    // dots2 (lower tri), then attn in-place
__device__ float g_uv  [SEQ*SEQ*HD];       // Uv[d][j][c], 134 MB
__device__ float g_out1[SEQ*DIM];
__device__ float g_out2[SEQ*HD];
__device__ float g_tmp [SEQ*DIM];

// ---------------- layernorm ----------------
__global__ void __launch_bounds__(256) ln_kernel(const float* __restrict__ x,
                                                 const float* __restrict__ w,
                                                 const float* __restrict__ b) {
    int row = blockIdx.x;
    int tid = threadIdx.x;
    const float* xr = x + row*DIM;
    __shared__ float red[20];
    float v0 = xr[tid], v1 = xr[tid+256];
    float s = v0 + v1;
    #pragma unroll
    for (int o=16;o;o>>=1) s += __shfl_xor_sync(0xffffffffu, s, o);
    if ((tid&31)==0) red[tid>>5] = s;
    __syncthreads();
    if (tid < 8) {
        s = red[tid];
        #pragma unroll
        for (int o=4;o;o>>=1) s += __shfl_xor_sync(0xffu, s, o);
        if (tid==0) red[16] = s;
    }
    __syncthreads();
    float mu = red[16] * (1.0f/DIM);
    float d0 = v0-mu, d1 = v1-mu;
    float q = d0*d0 + d1*d1;
    #pragma unroll
    for (int o=16;o;o>>=1) q += __shfl_xor_sync(0xffffffffu, q, o);
    if ((tid&31)==0) red[8 + (tid>>5)] = q;
    __syncthreads();
    if (tid < 8) {
        q = red[8+tid];
        #pragma unroll
        for (int o=4;o;o>>=1) q += __shfl_xor_sync(0xffu, q, o);
        if (tid==0) red[17] = q;
    }
    __syncthreads();
    float inv = rsqrtf(red[17]*(1.0f/DIM) + 1e-5f);
    g_xn[row*DIM + tid]     = d0*inv*w[tid]     + b[tid];
    g_xn[row*DIM + tid+256] = d1*inv*w[tid+256] + b[tid+256];
}

// ---------------- generic tiled SGEMM: C[M,N] = A[M,K] @ B[K,N] (+epilogue) ----------------
// tile 32x64, BK=32, 256 threads; EPI: 0 none, 1 C=(add+AB)*scale, 2 C=AB+bias[col]
template<int EPI>
__global__ void __launch_bounds__(256) sgemm(const float* __restrict__ A,
                                             const float* __restrict__ B,
                                             float* __restrict__ C,
                                             int N, int K,
                                             const float* __restrict__ add,
                                             float scale) {
    __shared__ float sA[32][36];
    __shared__ float sB[32][68];
    int m0 = blockIdx.y*32, n0 = blockIdx.x*64;
    int tid = threadIdx.x, ty = tid>>4, tx = tid&15;
    float acc[2][4] = {};
    for (int k0 = 0; k0 < K; k0 += 32) {
        __syncthreads();
        {   int r = tid>>3, c4 = tid&7;
            *(float4*)&sA[r][c4*4] = *(const float4*)(A + (m0+r)*K + k0 + c4*4); }
        #pragma unroll
        for (int qq=0; qq<2; qq++) {
            int idx = qq*256 + tid; int r = idx>>4, c4 = idx&15;
            *(float4*)&sB[r][c4*4] = *(const float4*)(B + (k0+r)*N + n0 + c4*4);
        }
        __syncthreads();
        #pragma unroll
        for (int kk=0; kk<32; kk++) {
            float a0 = sA[ty][kk], a1 = sA[ty+16][kk];
            float4 b4 = *(float4*)&sB[kk][tx*4];
            acc[0][0] += a0*b4.x; acc[0][1] += a0*b4.y; acc[0][2] += a0*b4.z; acc[0][3] += a0*b4.w;
            acc[1][0] += a1*b4.x; acc[1][1] += a1*b4.y; acc[1][2] += a1*b4.z; acc[1][3] += a1*b4.w;
        }
    }
    #pragma unroll
    for (int rr=0; rr<2; rr++) {
        int row = m0 + ty + rr*16;
        float4 r4 = make_float4(acc[rr][0], acc[rr][1], acc[rr][2], acc[rr][3]);
        if (EPI==1) {
            const float* ap = add + row*N + n0 + tx*4;
            r4.x = (r4.x + ap[0])*scale; r4.y = (r4.y + ap[1])*scale;
            r4.z = (r4.z + ap[2])*scale; r4.w = (r4.w + ap[3])*scale;
        } else if (EPI==2) {
            const float* bp = add + n0 + tx*4;
            r4.x += bp[0]; r4.y += bp[1]; r4.z += bp[2]; r4.w += bp[3];
        }
        *(float4*)(C + row*N + n0 + tx*4) = r4;
    }
}

// ---------------- per-diagonal rel-projection kernel ----------------
// For diagonal d: Uq = Aq[j+d,:] @ Pq[511-d], Uk = Ak[j,:] @ Pk[d], Uv = Av[j,:] @ Pv[d]
// dots2[h, j+d, j] = sum_{e<16} Uq[j][16h+e]*Uk[j][16h+e];  Uv tile -> g_uv[d][j][:]

__device__ __forceinline__ void load_A(const float* __restrict__ Abase, int rowbase, int nvalid,
                                       float (&sA)[32][132], int tid) {
    #pragma unroll
    for (int q=0; q<4; q++) {
        int idx = q*256 + tid;
        int r = idx>>5, c4 = idx&31;
        float4 v = make_float4(0.f,0.f,0.f,0.f);
        if (r < nvalid) v = *(const float4*)(Abase + (rowbase + r)*HD + c4*4);
        *(float4*)&sA[r][c4*4] = v;
    }
}

__device__ __forceinline__ void gemm_tile(const float* __restrict__ P,
                                          float (&sA)[32][132], float (&sP)[16][128],
                                          float acc[2][8], int tid, int ty, int tx) {
    for (int f0 = 0; f0 < 128; f0 += 16) {
        __syncthreads();
        #pragma unroll
        for (int q=0; q<2; q++) {
            int idx = q*256 + tid; int r = idx>>5, c4 = idx&31;
            *(float4*)&sP[r][c4*4] = *(const float4*)(P + (f0+r)*128 + c4*4);
        }
        __syncthreads();
        #pragma unroll
        for (int ff=0; ff<16; ff++) {
            float a0 = sA[ty][f0+ff];
            float a1 = sA[ty+16][f0+ff];
            float4 p0 = *(float4*)&sP[ff][tx*8];
            float4 p1 = *(float4*)&sP[ff][tx*8+4];
            acc[0][0]+=a0*p0.x; acc[0][1]+=a0*p0.y; acc[0][2]+=a0*p0.z; acc[0][3]+=a0*p0.w;
            acc[0][4]+=a0*p1.x; acc[0][5]+=a0*p1.y; acc[0][6]+=a0*p1.z; acc[0][7]+=a0*p1.w;
            acc[1][0]+=a1*p0.x; acc[1][1]+=a1*p0.y; acc[1][2]+=a1*p0.z; acc[1][3]+=a1*p0.w;
            acc[1][4]+=a1*p1.x; acc[1][5]+=a1*p1.y; acc[1][6]+=a1*p1.z; acc[1][7]+=a1*p1.w;
        }
    }
}

__global__ void __launch_bounds__(256) diag_kernel(const float* __restrict__ Pq,
                                                   const float* __restrict__ Pk,
                                                   const float* __restrict__ Pv) {
    int d  = blockIdx.y;
    int nj = SEQ - d;
    int j0 = blockIdx.x * 32;
    if (j0 >= nj) return;
    __shared__ float sA[32][132];
    __shared__ float sP[16][128];
    int tid = threadIdx.x, ty = tid>>4, tx = tid&15;
    int nvalid = min(32, nj - j0);

    float accQ[2][8] = {};
    load_A(g_aq, j0 + d, nvalid, sA, tid);
    gemm_tile(Pq + (size_t)(SEQ-1-d)*HD*HD, sA, sP, accQ, tid, ty, tx);
    __syncthreads();

    float accK[2][8] = {};
    load_A(g_ak, j0, nvalid, sA, tid);
    gemm_tile(Pk + (size_t)d*HD*HD, sA, sP, accK, tid, ty, tx);

    // dots2: this thread owns cols tx*8..tx*8+7, i.e. half of head h=tx>>1
    float p0 = 0.f, p1 = 0.f;
    #pragma unroll
    for (int c=0; c<8; c++) { p0 += accQ[0][c]*accK[0][c]; p1 += accQ[1][c]*accK[1][c]; }
    p0 += __shfl_xor_sync(0xffffffffu, p0, 1);
    p1 += __shfl_xor_sync(0xffffffffu, p1, 1);
    if ((tx & 1) == 0) {
        int h = tx >> 1;
        if (ty < nvalid)
            g_dots[h*SEQ*SEQ + (j0+ty+d)*SEQ + (j0+ty)] = p0;
        if (ty+16 < nvalid)
            g_dots[h*SEQ*SEQ + (j0+ty+16+d)*SEQ + (j0+ty+16)] = p1;
    }
    __syncthreads();

    float accV[2][8] = {};
    load_A(g_av, j0, nvalid, sA, tid);
    gemm_tile(Pv + (size_t)d*HD*HD, sA, sP, accV, tid, ty, tx);
    if (ty < nvalid) {
        float* dst = g_uv + ((size_t)d*SEQ + j0 + ty)*HD + tx*8;
        *(float4*)dst       = make_float4(accV[0][0],accV[0][1],accV[0][2],accV[0][3]);
        *(float4*)(dst + 4) = make_float4(accV[0][4],accV[0][5],accV[0][6],accV[0][7]);
    }
    if (ty+16 < nvalid) {
        float* dst = g_uv + ((size_t)d*SEQ + j0 + ty + 16)*HD + tx*8;
        *(float4*)dst       = make_float4(accV[1][0],accV[1][1],accV[1][2],accV[1][3]);
        *(float4*)(dst + 4) = make_float4(accV[1][4],accV[1][5],accV[1][6],accV[1][7]);
    }
}

// ---------------- dots1 + combine + causal softmax (attn written in place of g_dots) ------
__global__ void __launch_bounds__(256) attn_kernel() {
    int h  = blockIdx.y;
    int i0 = blockIdx.x * 16;
    __shared__ float sQ[16][68];
    __shared__ float sK[32][68];
    __shared__ float sD[16][512];
    int tid = threadIdx.x;
    {   int r = tid>>4, c4 = tid&15;
        *(float4*)&sQ[r][c4*4] = *(const float4*)(g_qkv + (i0+r)*1536 + h*64 + c4*4); }
    int r2 = tid>>4, jj = tid&15;
    for (int jc = 0; jc < 512; jc += 32) {
        __syncthreads();
        #pragma unroll
        for (int q=0; q<2; q++) {
            int idx = q*256 + tid; int r = idx>>4, c4 = idx&15;
            *(float4*)&sK[r][c4*4] = *(const float4*)(g_qkv + (jc+r)*1536 + 512 + h*64 + c4*4);
        }
        __syncthreads();
        float a0 = 0.f, a1 = 0.f;
        #pragma unroll
        for (int c=0; c<64; c++) {
            float qv = sQ[r2][c];
            a0 += qv * sK[jj][c];
            a1 += qv * sK[jj+16][c];
        }
        sD[r2][jc+jj]    = a0;
        sD[r2][jc+jj+16] = a1;
    }
    __syncthreads();
    int w = tid>>5, lane = tid&31;
    for (int rr = 2*w; rr < 2*w+2; rr++) {
        int i = i0 + rr;
        float vals[16];
        float m = -1e30f;
        #pragma unroll
        for (int t=0; t<16; t++) {
            int j = lane + t*32;
            float dv = -1e30f;
            if (j <= i)
                dv = 0.0625f * (sD[rr][j] + g_dots[h*SEQ*SEQ + i*SEQ + j]);
            vals[t] = dv;
            m = fmaxf(m, dv);
        }
        #pragma unroll
        for (int o=16;o;o>>=1) m = fmaxf(m, __shfl_xor_sync(0xffffffffu, m, o));
        float s = 0.f;
        #pragma unroll
        for (int t=0; t<16; t++) {
            float e = (vals[t] > -1e29f) ? __expf(vals[t]-m) : 0.f;
            vals[t] = e; s += e;
        }
        #pragma unroll
        for (int o=16;o;o>>=1) s += __shfl_xor_sync(0xffffffffu, s, o);
        float inv = 1.f / s;
        #pragma unroll
        for (int t=0; t<16; t++) {
            int j = lane + t*32;
            g_dots[h*SEQ*SEQ + i*SEQ + j] = vals[t]*inv;
        }
    }
}

// ---------------- out1 = attn @ v1 (per head) ----------------
__global__ void __launch_bounds__(256) out1_kernel() {
    int h = blockIdx.y, i0 = blockIdx.x*32;
    __shared__ float sAt[32][36];
    __shared__ float sV[32][68];
    int tid = threadIdx.x, ty = tid>>4, tx = tid&15;
    float acc[2][4] = {};
    for (int jc = 0; jc < 512; jc += 32) {
        __syncthreads();
        {   int r = tid>>3, c4 = tid&7;
            *(float4*)&sAt[r][c4*4] = *(const float4*)(g_dots + h*SEQ*SEQ + (i0+r)*512 + jc + c4*4); }
        #pragma unroll
        for (int q=0; q<2; q++) {
            int idx = q*256 + tid; int r = idx>>4, c4 = idx&15;
            *(float4*)&sV[r][c4*4] = *(const float4*)(g_qkv + (jc+r)*1536 + 1024 + h*64 + c4*4);
        }
        __syncthreads();
        #pragma unroll
        for (int k=0; k<32; k++) {
            float a0 = sAt[ty][k], a1 = sAt[ty+16][k];
            float4 v4 = *(float4*)&sV[k][tx*4];
            acc[0][0]+=a0*v4.x; acc[0][1]+=a0*v4.y; acc[0][2]+=a0*v4.z; acc[0][3]+=a0*v4.w;
            acc[1][0]+=a1*v4.x; acc[1][1]+=a1*v4.y; acc[1][2]+=a1*v4.z; acc[1][3]+=a1*v4.w;
        }
    }
    *(float4*)(g_out1 + (i0+ty)*512    + h*64 + tx*4) = make_float4(acc[0][0],acc[0][1],acc[0][2],acc[0][3]);
    *(float4*)(g_out1 + (i0+ty+16)*512 + h*64 + tx*4) = make_float4(acc[1][0],acc[1][1],acc[1][2],acc[1][3]);
}

// ---------------- out2[i,c] = sum_{j<=i} attn[h(c),i,j] * Uv[i-j][j][c] ----------------
__global__ void __launch_bounds__(128) out2_kernel() {
    int i = blockIdx.x;
    int c = threadIdx.x;
    int h = c >> 4;
    const float* arow = g_dots + h*SEQ*SEQ + i*SEQ;
    float a0=0.f, a1=0.f, a2=0.f, a3=0.f;
    int j = 0;
    for (; j+3 <= i; j += 4) {
        a0 += arow[j]   * g_uv[((size_t)(i-j  )*SEQ + j  )*HD + c];
        a1 += arow[j+1] * g_uv[((size_t)(i-j-1)*SEQ + j+1)*HD + c];
        a2 += arow[j+2] * g_uv[((size_t)(i-j-2)*SEQ + j+2)*HD + c];
        a3 += arow[j+3] * g_uv[((size_t)(i-j-3)*SEQ + j+3)*HD + c];
    }
    for (; j <= i; j++)
        a0 += arow[j] * g_uv[((size_t)(i-j)*SEQ + j)*HD + c];
    g_out2[i*HD + c] = (a0+a1) + (a2+a3);
}

// ---------------- launch ----------------
extern "C" void kernel_launch(void* const* d_in, const int* in_sizes, int n_in,
                              void* d_out, int out_size) {
    const float* x     = (const float*)d_in[0];
    const float* ln_w  = (const float*)d_in[1];
    const float* ln_b  = (const float*)d_in[2];
    const float* w_qkv = (const float*)d_in[3];
    const float* w_q1  = (const float*)d_in[4];
    const float* p_q2  = (const float*)d_in[5];
    const float* w_k1  = (const float*)d_in[6];
    const float* p_k2  = (const float*)d_in[7];
    const float* w_v1  = (const float*)d_in[8];
    const float* p_v2  = (const float*)d_in[9];
    const float* w_v3  = (const float*)d_in[10];
    const float* w_out = (const float*)d_in[11];
    const float* b_out = (const float*)d_in[12];
    float* out = (float*)d_out;

    float *p_xn, *p_qkvb, *p_aq, *p_ak, *p_av, *p_out1b, *p_out2b, *p_tmpb;
    cudaGetSymbolAddress((void**)&p_xn,   g_xn);
    cudaGetSymbolAddress((void**)&p_qkvb, g_qkv);
    cudaGetSymbolAddress((void**)&p_aq,   g_aq);
    cudaGetSymbolAddress((void**)&p_ak,   g_ak);
    cudaGetSymbolAddress((void**)&p_av,   g_av);
    cudaGetSymbolAddress((void**)&p_out1b,g_out1);
    cudaGetSymbolAddress((void**)&p_out2b,g_out2);
    cudaGetSymbolAddress((void**)&p_tmpb, g_tmp);

    ln_kernel<<<512, 256>>>(x, ln_w, ln_b);

    sgemm<0><<<dim3(24,16), 256>>>(p_xn, w_qkv, p_qkvb, 1536, 512, nullptr, 0.f);
    sgemm<0><<<dim3(2,16),  256>>>(p_xn, w_q1,  p_aq,   128,  512, nullptr, 0.f);
    sgemm<0><<<dim3(2,16),  256>>>(p_xn, w_k1,  p_ak,   128,  512, nullptr, 0.f);
    sgemm<0><<<dim3(2,16),  256>>>(p_xn, w_v1,  p_av,   128,  512, nullptr, 0.f);

    diag_kernel<<<dim3(16,512), 256>>>(p_q2, p_k2, p_v2);

    attn_kernel<<<dim3(32,8), 256>>>();
    out1_kernel<<<dim3(16,8), 256>>>();
    out2_kernel<<<512, 128>>>();

    // tmp = (out1 + out2 @ w_v3) * 0.5
    sgemm<1><<<dim3(8,16), 256>>>(p_out2b, w_v3, p_tmpb, 512, 128, p_out1b, 0.5f);
    // out = tmp @ w_out + b_out
    sgemm<2><<<dim3(8,16), 256>>>(p_tmpb, w_out, out, 512, 512, b_out, 0.f);
}

// round 4
// speedup vs baseline: 2.8396x; 2.8396x over previous
#include <cuda_runtime.h>

#define SEQ   512
#define DIM   512
#define HEADS 8
#define DH    64
#define DR    16
#define HD    128

// ---------------- device scratch ----------------
__device__ float g_xn  [SEQ*DIM];
__device__ float g_qkv [SEQ*3*DIM];        // q1|k1|v1
__device__ float g_aq  [SEQ*HD];
__device__ float g_ak  [SEQ*HD];
__device__ float g_av  [SEQ*HD];
__device__ float g_dots[HEADS*SEQ*SEQ];    // dots2 lower-tri, then attn in place
__device__ float g_uv  [(size_t)SEQ*SEQ*HD];
__device__ float g_out1[SEQ*DIM];
__device__ float g_out2[SEQ*HD];
__device__ float g_tmp [SEQ*DIM];

// ---------------- helpers ----------------
__device__ __forceinline__ float to_tf32(float x) {
    unsigned u;
    asm("cvt.rna.tf32.f32 %0, %1;" : "=r"(u) : "f"(x));
    return __uint_as_float(u);
}
__device__ __forceinline__ void mma_tf32(float c[4], unsigned a0, unsigned a1, unsigned a2, unsigned a3,
                                         unsigned b0, unsigned b1) {
    asm volatile("mma.sync.aligned.m16n8k8.row.col.f32.tf32.tf32.f32 "
                 "{%0,%1,%2,%3}, {%4,%5,%6,%7}, {%8,%9}, {%0,%1,%2,%3};"
                 : "+f"(c[0]), "+f"(c[1]), "+f"(c[2]), "+f"(c[3])
                 : "r"(a0), "r"(a1), "r"(a2), "r"(a3), "r"(b0), "r"(b1));
}

// ---------------- layernorm ----------------
__global__ void __launch_bounds__(256) ln_kernel(const float* __restrict__ x,
                                                 const float* __restrict__ w,
                                                 const float* __restrict__ b) {
    int row = blockIdx.x;
    int tid = threadIdx.x;
    const float* xr = x + row*DIM;
    __shared__ float red[20];
    float v0 = xr[tid], v1 = xr[tid+256];
    float s = v0 + v1;
    #pragma unroll
    for (int o=16;o;o>>=1) s += __shfl_xor_sync(0xffffffffu, s, o);
    if ((tid&31)==0) red[tid>>5] = s;
    __syncthreads();
    if (tid < 8) {
        s = red[tid];
        #pragma unroll
        for (int o=4;o;o>>=1) s += __shfl_xor_sync(0xffu, s, o);
        if (tid==0) red[16] = s;
    }
    __syncthreads();
    float mu = red[16] * (1.0f/DIM);
    float d0 = v0-mu, d1 = v1-mu;
    float q = d0*d0 + d1*d1;
    #pragma unroll
    for (int o=16;o;o>>=1) q += __shfl_xor_sync(0xffffffffu, q, o);
    if ((tid&31)==0) red[8 + (tid>>5)] = q;
    __syncthreads();
    if (tid < 8) {
        q = red[8+tid];
        #pragma unroll
        for (int o=4;o;o>>=1) q += __shfl_xor_sync(0xffu, q, o);
        if (tid==0) red[17] = q;
    }
    __syncthreads();
    float inv = rsqrtf(red[17]*(1.0f/DIM) + 1e-5f);
    g_xn[row*DIM + tid]     = d0*inv*w[tid]     + b[tid];
    g_xn[row*DIM + tid+256] = d1*inv*w[tid+256] + b[tid+256];
}

// ---------------- generic tf32 MMA GEMM: C[M,N] = A[M,K] @ B[K,N], tile 64x64 ----------------
// 256 threads = 8 warps: 4 warp-rows (m16) x 2 warp-cols (n32, 4 n-frags each)
// EPI: 0 none, 1 C=(add+AB)*0.5 (add is MxN), 2 C=AB+bias[col]
struct SmemGemm { float sA[64][36]; float sB[32][68]; };

template<int EPI>
__device__ __forceinline__ void gemm_body(const float* __restrict__ A, const float* __restrict__ B,
                                          float* __restrict__ C, int N, int K,
                                          const float* __restrict__ add,
                                          SmemGemm& sm, int m0, int n0) {
    int tid = threadIdx.x;
    int warp = tid>>5, lane = tid&31;
    int qrow = lane>>2, qcol = lane&3;
    int m_base = (warp&3)*16, n_base = (warp>>2)*32;
    float acc[4][4] = {};
    for (int kc = 0; kc < K; kc += 32) {
        __syncthreads();
        #pragma unroll
        for (int q=0;q<2;q++) {
            int idx = q*256+tid; int r = idx>>3, c4 = idx&7;
            float4 v = *(const float4*)(A + (m0+r)*K + kc + c4*4);
            sm.sA[r][c4*4+0]=to_tf32(v.x); sm.sA[r][c4*4+1]=to_tf32(v.y);
            sm.sA[r][c4*4+2]=to_tf32(v.z); sm.sA[r][c4*4+3]=to_tf32(v.w);
        }
        #pragma unroll
        for (int q=0;q<2;q++) {
            int idx = q*256+tid; int r = idx>>4, c4 = idx&15;
            float4 v = *(const float4*)(B + (kc+r)*N + n0 + c4*4);
            sm.sB[r][c4*4+0]=to_tf32(v.x); sm.sB[r][c4*4+1]=to_tf32(v.y);
            sm.sB[r][c4*4+2]=to_tf32(v.z); sm.sB[r][c4*4+3]=to_tf32(v.w);
        }
        __syncthreads();
        #pragma unroll
        for (int ks=0; ks<4; ks++) {
            int k0 = ks*8;
            unsigned a0 = __float_as_uint(sm.sA[m_base+qrow  ][k0+qcol  ]);
            unsigned a1 = __float_as_uint(sm.sA[m_base+qrow+8][k0+qcol  ]);
            unsigned a2 = __float_as_uint(sm.sA[m_base+qrow  ][k0+qcol+4]);
            unsigned a3 = __float_as_uint(sm.sA[m_base+qrow+8][k0+qcol+4]);
            #pragma unroll
            for (int nf=0; nf<4; nf++) {
                unsigned b0 = __float_as_uint(sm.sB[k0+qcol  ][n_base+nf*8+qrow]);
                unsigned b1 = __float_as_uint(sm.sB[k0+qcol+4][n_base+nf*8+qrow]);
                mma_tf32(acc[nf], a0,a1,a2,a3, b0,b1);
            }
        }
    }
    #pragma unroll
    for (int nf=0; nf<4; nf++) {
        int col = n0 + n_base + nf*8 + 2*qcol;
        int r0 = m0 + m_base + qrow, r1 = r0 + 8;
        float2 v0 = make_float2(acc[nf][0], acc[nf][1]);
        float2 v1 = make_float2(acc[nf][2], acc[nf][3]);
        if (EPI==1) {
            const float* p0 = add + (size_t)r0*N + col;
            const float* p1 = add + (size_t)r1*N + col;
            v0.x = (v0.x + p0[0])*0.5f; v0.y = (v0.y + p0[1])*0.5f;
            v1.x = (v1.x + p1[0])*0.5f; v1.y = (v1.y + p1[1])*0.5f;
        } else if (EPI==2) {
            v0.x += add[col]; v0.y += add[col+1];
            v1.x += add[col]; v1.y += add[col+1];
        }
        *(float2*)(C + (size_t)r0*N + col) = v0;
        *(float2*)(C + (size_t)r1*N + col) = v1;
    }
}

template<int EPI>
__global__ void __launch_bounds__(256) mma_gemm(const float* __restrict__ A, const float* __restrict__ B,
                                                float* __restrict__ C, int N, int K,
                                                const float* __restrict__ add) {
    __shared__ SmemGemm sm;
    gemm_body<EPI>(A, B, C, N, K, add, sm, blockIdx.y*64, blockIdx.x*64);
}

// fused q1/k1/v1 projections (z selects weight/output)
__global__ void __launch_bounds__(256) mma_gemm3(const float* __restrict__ A,
                                                 const float* __restrict__ B0, const float* __restrict__ B1,
                                                 const float* __restrict__ B2,
                                                 float* C0, float* C1, float* C2, int N, int K) {
    __shared__ SmemGemm sm;
    const float* B = blockIdx.z==0 ? B0 : (blockIdx.z==1 ? B1 : B2);
    float* C       = blockIdx.z==0 ? C0 : (blockIdx.z==1 ? C1 : C2);
    gemm_body<0>(A, B, C, N, K, nullptr, sm, blockIdx.y*64, blockIdx.x*64);
}

// ---------------- per-diagonal rel-projection via tf32 MMA ----------------
// Block: diagonal d (blockIdx.y), row chunk j0=blockIdx.x*64, tile 64x128x128
// smem: sA 64x132 (33.0 KB) + sP 16x132 (8.25 KB) = 41.25 KB < 48 KB
__global__ void __launch_bounds__(256) diag_mma(const float* __restrict__ Pq,
                                                const float* __restrict__ Pk,
                                                const float* __restrict__ Pv) {
    int d  = blockIdx.y;
    int nj = SEQ - d;
    int j0 = blockIdx.x * 64;
    if (j0 >= nj) return;
    int nvalid = min(64, nj - j0);

    __shared__ float sA[64][132];
    __shared__ float sP[16][132];
    int tid = threadIdx.x, warp = tid>>5, lane = tid&31;
    int qrow = lane>>2, qcol = lane&3;
    int m_base = (warp&3)*16, n_base = (warp>>2)*64;

    auto loadA = [&](const float* __restrict__ Ab, int rowbase) {
        #pragma unroll
        for (int q=0;q<8;q++) {
            int idx = q*256+tid; int r = idx>>5, c4 = idx&31;
            float4 v = make_float4(0.f,0.f,0.f,0.f);
            if (r < nvalid) v = *(const float4*)(Ab + (rowbase+r)*HD + c4*4);
            sA[r][c4*4+0]=to_tf32(v.x); sA[r][c4*4+1]=to_tf32(v.y);
            sA[r][c4*4+2]=to_tf32(v.z); sA[r][c4*4+3]=to_tf32(v.w);
        }
    };
    auto gemm = [&](const float* __restrict__ P, float acc[8][4]) {
        for (int kc=0; kc<128; kc+=16) {
            __syncthreads();
            #pragma unroll
            for (int q=0;q<2;q++) {
                int idx = q*256+tid; int r = idx>>5, c4 = idx&31;
                float4 v = *(const float4*)(P + (kc+r)*HD + c4*4);
                sP[r][c4*4+0]=to_tf32(v.x); sP[r][c4*4+1]=to_tf32(v.y);
                sP[r][c4*4+2]=to_tf32(v.z); sP[r][c4*4+3]=to_tf32(v.w);
            }
            __syncthreads();
            #pragma unroll
            for (int ks=0; ks<2; ks++) {
                int k0 = kc + ks*8;
                unsigned a0 = __float_as_uint(sA[m_base+qrow  ][k0+qcol  ]);
                unsigned a1 = __float_as_uint(sA[m_base+qrow+8][k0+qcol  ]);
                unsigned a2 = __float_as_uint(sA[m_base+qrow  ][k0+qcol+4]);
                unsigned a3 = __float_as_uint(sA[m_base+qrow+8][k0+qcol+4]);
                #pragma unroll
                for (int nf=0; nf<8; nf++) {
                    unsigned b0 = __float_as_uint(sP[ks*8+qcol  ][n_base+nf*8+qrow]);
                    unsigned b1 = __float_as_uint(sP[ks*8+qcol+4][n_base+nf*8+qrow]);
                    mma_tf32(acc[nf], a0,a1,a2,a3, b0,b1);
                }
            }
        }
    };

    // Q: rows j0+d..  with Pq[511-d]
    float accQ[8][4] = {};
    loadA(g_aq, j0 + d);
    gemm(Pq + (size_t)(SEQ-1-d)*HD*HD, accQ);
    __syncthreads();

    // K: rows j0..  with Pk[d]
    float accK[8][4] = {};
    loadA(g_ak, j0);
    gemm(Pk + (size_t)d*HD*HD, accK);

    // dots2[h, j+d, j] = per-head (16 cols) dot of Uq,Uk rows
    #pragma unroll
    for (int hh=0; hh<4; hh++) {
        int f0 = 2*hh, f1 = 2*hh+1;
        float p0 = accQ[f0][0]*accK[f0][0] + accQ[f0][1]*accK[f0][1]
                 + accQ[f1][0]*accK[f1][0] + accQ[f1][1]*accK[f1][1];
        float p1 = accQ[f0][2]*accK[f0][2] + accQ[f0][3]*accK[f0][3]
                 + accQ[f1][2]*accK[f1][2] + accQ[f1][3]*accK[f1][3];
        p0 += __shfl_xor_sync(0xffffffffu, p0, 1);
        p0 += __shfl_xor_sync(0xffffffffu, p0, 2);
        p1 += __shfl_xor_sync(0xffffffffu, p1, 1);
        p1 += __shfl_xor_sync(0xffffffffu, p1, 2);
        if (qcol == 0) {
            int h = (n_base>>4) + hh;
            int r0 = m_base + qrow;
            if (r0 < nvalid) { int j = j0 + r0; g_dots[(size_t)h*SEQ*SEQ + (size_t)(j+d)*SEQ + j] = p0; }
            int r1 = r0 + 8;
            if (r1 < nvalid) { int j = j0 + r1; g_dots[(size_t)h*SEQ*SEQ + (size_t)(j+d)*SEQ + j] = p1; }
        }
    }
    __syncthreads();

    // V: rows j0..  with Pv[d] -> g_uv[d][j][:]
    float accV[8][4] = {};
    loadA(g_av, j0);
    gemm(Pv + (size_t)d*HD*HD, accV);
    #pragma unroll
    for (int nf=0; nf<8; nf++) {
        int col = n_base + nf*8 + 2*qcol;
        int r0 = m_base + qrow;
        if (r0 < nvalid)
            *(float2*)(g_uv + ((size_t)d*SEQ + j0 + r0)*HD + col) = make_float2(accV[nf][0], accV[nf][1]);
        int r1 = r0 + 8;
        if (r1 < nvalid)
            *(float2*)(g_uv + ((size_t)d*SEQ + j0 + r1)*HD + col) = make_float2(accV[nf][2], accV[nf][3]);
    }
}

// ---------------- dots1 + combine + causal softmax ----------------
__global__ void __launch_bounds__(256) attn_kernel() {
    int h  = blockIdx.y;
    int i0 = blockIdx.x * 16;
    __shared__ float sQ[16][68];
    __shared__ float sK[32][68];
    __shared__ float sD[16][512];
    int tid = threadIdx.x;
    {   int r = tid>>4, c4 = tid&15;
        *(float4*)&sQ[r][c4*4] = *(const float4*)(g_qkv + (i0+r)*1536 + h*64 + c4*4); }
    int r2 = tid>>4, jj = tid&15;
    for (int jc = 0; jc < 512; jc += 32) {
        __syncthreads();
        #pragma unroll
        for (int q=0; q<2; q++) {
            int idx = q*256 + tid; int r = idx>>4, c4 = idx&15;
            *(float4*)&sK[r][c4*4] = *(const float4*)(g_qkv + (jc+r)*1536 + 512 + h*64 + c4*4);
        }
        __syncthreads();
        float a0 = 0.f, a1 = 0.f;
        #pragma unroll
        for (int c=0; c<64; c++) {
            float qv = sQ[r2][c];
            a0 += qv * sK[jj][c];
            a1 += qv * sK[jj+16][c];
        }
        sD[r2][jc+jj]    = a0;
        sD[r2][jc+jj+16] = a1;
    }
    __syncthreads();
    int w = tid>>5, lane = tid&31;
    for (int rr = 2*w; rr < 2*w+2; rr++) {
        int i = i0 + rr;
        float vals[16];
        float m = -1e30f;
        #pragma unroll
        for (int t=0; t<16; t++) {
            int j = lane + t*32;
            float dv = -1e30f;
            if (j <= i)
                dv = 0.0625f * (sD[rr][j] + g_dots[(size_t)h*SEQ*SEQ + (size_t)i*SEQ + j]);
            vals[t] = dv;
            m = fmaxf(m, dv);
        }
        #pragma unroll
        for (int o=16;o;o>>=1) m = fmaxf(m, __shfl_xor_sync(0xffffffffu, m, o));
        float s = 0.f;
        #pragma unroll
        for (int t=0; t<16; t++) {
            float e = (vals[t] > -1e29f) ? __expf(vals[t]-m) : 0.f;
            vals[t] = e; s += e;
        }
        #pragma unroll
        for (int o=16;o;o>>=1) s += __shfl_xor_sync(0xffffffffu, s, o);
        float inv = 1.f / s;
        #pragma unroll
        for (int t=0; t<16; t++) {
            int j = lane + t*32;
            g_dots[(size_t)h*SEQ*SEQ + (size_t)i*SEQ + j] = vals[t]*inv;
        }
    }
}

// ---------------- out1 = attn @ v1 ----------------
__global__ void __launch_bounds__(256) out1_kernel() {
    int h = blockIdx.y, i0 = blockIdx.x*32;
    __shared__ float sAt[32][36];
    __shared__ float sV[32][68];
    int tid = threadIdx.x, ty = tid>>4, tx = tid&15;
    float acc[2][4] = {};
    for (int jc = 0; jc < 512; jc += 32) {
        __syncthreads();
        {   int r = tid>>3, c4 = tid&7;
            *(float4*)&sAt[r][c4*4] = *(const float4*)(g_dots + (size_t)h*SEQ*SEQ + (size_t)(i0+r)*512 + jc + c4*4); }
        #pragma unroll
        for (int q=0; q<2; q++) {
            int idx = q*256 + tid; int r = idx>>4, c4 = idx&15;
            *(float4*)&sV[r][c4*4] = *(const float4*)(g_qkv + (jc+r)*1536 + 1024 + h*64 + c4*4);
        }
        __syncthreads();
        #pragma unroll
        for (int k=0; k<32; k++) {
            float a0 = sAt[ty][k], a1 = sAt[ty+16][k];
            float4 v4 = *(float4*)&sV[k][tx*4];
            acc[0][0]+=a0*v4.x; acc[0][1]+=a0*v4.y; acc[0][2]+=a0*v4.z; acc[0][3]+=a0*v4.w;
            acc[1][0]+=a1*v4.x; acc[1][1]+=a1*v4.y; acc[1][2]+=a1*v4.z; acc[1][3]+=a1*v4.w;
        }
    }
    *(float4*)(g_out1 + (i0+ty)*512    + h*64 + tx*4) = make_float4(acc[0][0],acc[0][1],acc[0][2],acc[0][3]);
    *(float4*)(g_out1 + (i0+ty+16)*512 + h*64 + tx*4) = make_float4(acc[1][0],acc[1][1],acc[1][2],acc[1][3]);
}

// ---------------- out2[i,c] = sum_{j<=i} attn[h(c),i,j] * Uv[i-j][j][c] ----------------
__global__ void __launch_bounds__(512) out2_kernel() {
    int i = blockIdx.x;
    int tid = threadIdx.x;
    int c = tid & 127;
    int part = tid >> 7;
    int h = c >> 4;
    const float* arow = g_dots + (size_t)h*SEQ*SEQ + (size_t)i*SEQ;
    int len = i + 1;
    int chunk = (len + 3) >> 2;
    int jb = part*chunk, je = min(len, jb + chunk);
    float a0=0.f, a1=0.f, a2=0.f, a3=0.f;
    int j = jb;
    for (; j+4 <= je; j += 4) {
        a0 += arow[j]   * g_uv[((size_t)(i-j  )*SEQ + j  )*HD + c];
        a1 += arow[j+1] * g_uv[((size_t)(i-j-1)*SEQ + j+1)*HD + c];
        a2 += arow[j+2] * g_uv[((size_t)(i-j-2)*SEQ + j+2)*HD + c];
        a3 += arow[j+3] * g_uv[((size_t)(i-j-3)*SEQ + j+3)*HD + c];
    }
    for (; j < je; j++)
        a0 += arow[j] * g_uv[((size_t)(i-j)*SEQ + j)*HD + c];
    __shared__ float red[512];
    red[tid] = (a0+a1) + (a2+a3);
    __syncthreads();
    if (part == 0)
        g_out2[i*HD + c] = (red[c] + red[c+128]) + (red[c+256] + red[c+384]);
}

// ---------------- launch ----------------
extern "C" void kernel_launch(void* const* d_in, const int* in_sizes, int n_in,
                              void* d_out, int out_size) {
    const float* x     = (const float*)d_in[0];
    const float* ln_w  = (const float*)d_in[1];
    const float* ln_b  = (const float*)d_in[2];
    const float* w_qkv = (const float*)d_in[3];
    const float* w_q1  = (const float*)d_in[4];
    const float* p_q2  = (const float*)d_in[5];
    const float* w_k1  = (const float*)d_in[6];
    const float* p_k2  = (const float*)d_in[7];
    const float* w_v1  = (const float*)d_in[8];
    const float* p_v2  = (const float*)d_in[9];
    const float* w_v3  = (const float*)d_in[10];
    const float* w_out = (const float*)d_in[11];
    const float* b_out = (const float*)d_in[12];
    float* out = (float*)d_out;

    float *p_xn, *p_qkvb, *p_aq, *p_ak, *p_av, *p_out1b, *p_out2b, *p_tmpb;
    cudaGetSymbolAddress((void**)&p_xn,   g_xn);
    cudaGetSymbolAddress((void**)&p_qkvb, g_qkv);
    cudaGetSymbolAddress((void**)&p_aq,   g_aq);
    cudaGetSymbolAddress((void**)&p_ak,   g_ak);
    cudaGetSymbolAddress((void**)&p_av,   g_av);
    cudaGetSymbolAddress((void**)&p_out1b,g_out1);
    cudaGetSymbolAddress((void**)&p_out2b,g_out2);
    cudaGetSymbolAddress((void**)&p_tmpb, g_tmp);

    ln_kernel<<<512, 256>>>(x, ln_w, ln_b);

    // qkv = xn @ w_qkv  (512x1536x512)
    mma_gemm<0><<<dim3(24,8), 256>>>(p_xn, w_qkv, p_qkvb, 1536, 512, nullptr);
    // aq/ak/av = xn @ {w_q1,w_k1,w_v1}  (512x128x512, fused)
    mma_gemm3<<<dim3(2,8,3), 256>>>(p_xn, w_q1, w_k1, w_v1, p_aq, p_ak, p_av, 128, 512);

    diag_mma<<<dim3(8,512), 256>>>(p_q2, p_k2, p_v2);

    attn_kernel<<<dim3(32,8), 256>>>();
    out1_kernel<<<dim3(16,8), 256>>>();
    out2_kernel<<<512, 512>>>();

    // tmp = (out1 + out2 @ w_v3) * 0.5   (512x512x128)
    mma_gemm<1><<<dim3(8,8), 256>>>(p_out2b, w_v3, p_tmpb, 512, 128, p_out1b);
    // out = tmp @ w_out + b_out          (512x512x512)
    mma_gemm<2><<<dim3(8,8), 256>>>(p_tmpb, w_out, out, 512, 512, b_out);
}

// round 5
// speedup vs baseline: 3.5209x; 1.2399x over previous
#include <cuda_runtime.h>

#define SEQ   512
#define DIM   512
#define HEADS 8
#define DH    64
#define DR    16
#define HD    128

// ---------------- device scratch ----------------
__device__ float g_xn  [SEQ*DIM];
__device__ float g_qkv [SEQ*3*DIM];        // q1|k1|v1
__device__ float g_aq  [SEQ*HD];
__device__ float g_ak  [SEQ*HD];
__device__ float g_av  [SEQ*HD];
__device__ float g_dots[HEADS*SEQ*SEQ];    // dots2 lower-tri, then attn in place
__device__ float g_uv  [(size_t)SEQ*SEQ*HD];
__device__ float g_out1[SEQ*DIM];
__device__ float g_out2[SEQ*HD];
__device__ float g_tmp [SEQ*DIM];

// ---------------- helpers ----------------
__device__ __forceinline__ float to_tf32(float x) {
    unsigned u;
    asm("cvt.rna.tf32.f32 %0, %1;" : "=r"(u) : "f"(x));
    return __uint_as_float(u);
}
__device__ __forceinline__ void mma_tf32(float c[4], unsigned a0, unsigned a1, unsigned a2, unsigned a3,
                                         unsigned b0, unsigned b1) {
    asm volatile("mma.sync.aligned.m16n8k8.row.col.f32.tf32.tf32.f32 "
                 "{%0,%1,%2,%3}, {%4,%5,%6,%7}, {%8,%9}, {%0,%1,%2,%3};"
                 : "+f"(c[0]), "+f"(c[1]), "+f"(c[2]), "+f"(c[3])
                 : "r"(a0), "r"(a1), "r"(a2), "r"(a3), "r"(b0), "r"(b1));
}

// ---------------- layernorm ----------------
__global__ void __launch_bounds__(256) ln_kernel(const float* __restrict__ x,
                                                 const float* __restrict__ w,
                                                 const float* __restrict__ b) {
    int row = blockIdx.x;
    int tid = threadIdx.x;
    const float* xr = x + row*DIM;
    __shared__ float red[20];
    float v0 = xr[tid], v1 = xr[tid+256];
    float s = v0 + v1;
    #pragma unroll
    for (int o=16;o;o>>=1) s += __shfl_xor_sync(0xffffffffu, s, o);
    if ((tid&31)==0) red[tid>>5] = s;
    __syncthreads();
    if (tid < 8) {
        s = red[tid];
        #pragma unroll
        for (int o=4;o;o>>=1) s += __shfl_xor_sync(0xffu, s, o);
        if (tid==0) red[16] = s;
    }
    __syncthreads();
    float mu = red[16] * (1.0f/DIM);
    float d0 = v0-mu, d1 = v1-mu;
    float q = d0*d0 + d1*d1;
    #pragma unroll
    for (int o=16;o;o>>=1) q += __shfl_xor_sync(0xffffffffu, q, o);
    if ((tid&31)==0) red[8 + (tid>>5)] = q;
    __syncthreads();
    if (tid < 8) {
        q = red[8+tid];
        #pragma unroll
        for (int o=4;o;o>>=1) q += __shfl_xor_sync(0xffu, q, o);
        if (tid==0) red[17] = q;
    }
    __syncthreads();
    float inv = rsqrtf(red[17]*(1.0f/DIM) + 1e-5f);
    g_xn[row*DIM + tid]     = d0*inv*w[tid]     + b[tid];
    g_xn[row*DIM + tid+256] = d1*inv*w[tid+256] + b[tid+256];
}

// ---------------- generic tf32 MMA GEMM: C[M,N] = A[M,K] @ B[K,N], tile 64x64 ----------------
struct SmemGemm { float sA[64][36]; float sB[32][68]; };

template<int EPI>
__device__ __forceinline__ void gemm_body(const float* __restrict__ A, const float* __restrict__ B,
                                          float* __restrict__ C, int N, int K,
                                          const float* __restrict__ add,
                                          SmemGemm& sm, int m0, int n0) {
    int tid = threadIdx.x;
    int warp = tid>>5, lane = tid&31;
    int qrow = lane>>2, qcol = lane&3;
    int m_base = (warp&3)*16, n_base = (warp>>2)*32;
    float acc[4][4] = {};
    for (int kc = 0; kc < K; kc += 32) {
        __syncthreads();
        #pragma unroll
        for (int q=0;q<2;q++) {
            int idx = q*256+tid; int r = idx>>3, c4 = idx&7;
            float4 v = *(const float4*)(A + (m0+r)*K + kc + c4*4);
            sm.sA[r][c4*4+0]=to_tf32(v.x); sm.sA[r][c4*4+1]=to_tf32(v.y);
            sm.sA[r][c4*4+2]=to_tf32(v.z); sm.sA[r][c4*4+3]=to_tf32(v.w);
        }
        #pragma unroll
        for (int q=0;q<2;q++) {
            int idx = q*256+tid; int r = idx>>4, c4 = idx&15;
            float4 v = *(const float4*)(B + (kc+r)*N + n0 + c4*4);
            sm.sB[r][c4*4+0]=to_tf32(v.x); sm.sB[r][c4*4+1]=to_tf32(v.y);
            sm.sB[r][c4*4+2]=to_tf32(v.z); sm.sB[r][c4*4+3]=to_tf32(v.w);
        }
        __syncthreads();
        #pragma unroll
        for (int ks=0; ks<4; ks++) {
            int k0 = ks*8;
            unsigned a0 = __float_as_uint(sm.sA[m_base+qrow  ][k0+qcol  ]);
            unsigned a1 = __float_as_uint(sm.sA[m_base+qrow+8][k0+qcol  ]);
            unsigned a2 = __float_as_uint(sm.sA[m_base+qrow  ][k0+qcol+4]);
            unsigned a3 = __float_as_uint(sm.sA[m_base+qrow+8][k0+qcol+4]);
            #pragma unroll
            for (int nf=0; nf<4; nf++) {
                unsigned b0 = __float_as_uint(sm.sB[k0+qcol  ][n_base+nf*8+qrow]);
                unsigned b1 = __float_as_uint(sm.sB[k0+qcol+4][n_base+nf*8+qrow]);
                mma_tf32(acc[nf], a0,a1,a2,a3, b0,b1);
            }
        }
    }
    #pragma unroll
    for (int nf=0; nf<4; nf++) {
        int col = n0 + n_base + nf*8 + 2*qcol;
        int r0 = m0 + m_base + qrow, r1 = r0 + 8;
        float2 v0 = make_float2(acc[nf][0], acc[nf][1]);
        float2 v1 = make_float2(acc[nf][2], acc[nf][3]);
        if (EPI==1) {
            const float* p0 = add + (size_t)r0*N + col;
            const float* p1 = add + (size_t)r1*N + col;
            v0.x = (v0.x + p0[0])*0.5f; v0.y = (v0.y + p0[1])*0.5f;
            v1.x = (v1.x + p1[0])*0.5f; v1.y = (v1.y + p1[1])*0.5f;
        } else if (EPI==2) {
            v0.x += add[col]; v0.y += add[col+1];
            v1.x += add[col]; v1.y += add[col+1];
        }
        *(float2*)(C + (size_t)r0*N + col) = v0;
        *(float2*)(C + (size_t)r1*N + col) = v1;
    }
}

template<int EPI>
__global__ void __launch_bounds__(256) mma_gemm(const float* __restrict__ A, const float* __restrict__ B,
                                                float* __restrict__ C, int N, int K,
                                                const float* __restrict__ add) {
    __shared__ SmemGemm sm;
    gemm_body<EPI>(A, B, C, N, K, add, sm, blockIdx.y*64, blockIdx.x*64);
}

// fused q1/k1/v1 projections (z selects weight/output)
__global__ void __launch_bounds__(256) mma_gemm3(const float* __restrict__ A,
                                                 const float* __restrict__ B0, const float* __restrict__ B1,
                                                 const float* __restrict__ B2,
                                                 float* C0, float* C1, float* C2, int N, int K) {
    __shared__ SmemGemm sm;
    const float* B = blockIdx.z==0 ? B0 : (blockIdx.z==1 ? B1 : B2);
    float* C       = blockIdx.z==0 ? C0 : (blockIdx.z==1 ? C1 : C2);
    gemm_body<0>(A, B, C, N, K, nullptr, sm, blockIdx.y*64, blockIdx.x*64);
}

// ---------------- per-diagonal rel-projection via tf32 MMA ----------------
// Block: 128 threads = 4 warps; tile m64 x n128 x k128.
// Warp w: m_base=(w&1)*32 (2 m-frags), n_base=(w>>1)*64 (8 n-frags) -> 16 mma/kstep.
// P panel streamed through smem in 16-row chunks with register prefetch.
__global__ void __launch_bounds__(128) diag_mma(const float* __restrict__ Pq,
                                                const float* __restrict__ Pk,
                                                const float* __restrict__ Pv) {
    int d  = blockIdx.y;
    int nj = SEQ - d;
    int j0 = blockIdx.x * 64;
    if (j0 >= nj) return;
    int nvalid = min(64, nj - j0);

    __shared__ float sA[64][132];
    __shared__ float sP[16][132];
    int tid = threadIdx.x, warp = tid>>5, lane = tid&31;
    int qrow = lane>>2, qcol = lane&3;
    int m_base = (warp&1)*32, n_base = (warp>>1)*64;

    auto loadA = [&](const float* __restrict__ Ab, int rowbase) {
        #pragma unroll
        for (int q=0;q<16;q++) {
            int idx = q*128+tid; int r = idx>>5, c4 = idx&31;
            float4 v = make_float4(0.f,0.f,0.f,0.f);
            if (r < nvalid) v = *(const float4*)(Ab + (rowbase+r)*HD + c4*4);
            sA[r][c4*4+0]=to_tf32(v.x); sA[r][c4*4+1]=to_tf32(v.y);
            sA[r][c4*4+2]=to_tf32(v.z); sA[r][c4*4+3]=to_tf32(v.w);
        }
    };

    // acc layout: acc[mf*8+nf][4], mf in {0,1} (rows m_base+mf*16), nf in {0..7}
    auto gemm = [&](const float* __restrict__ P, float acc[16][4]) {
        float4 pre[4];
        #pragma unroll
        for (int q=0;q<4;q++) {
            int idx = q*128+tid; int r = idx>>5, c4 = idx&31;
            pre[q] = *(const float4*)(P + r*HD + c4*4);
        }
        for (int kc=0; kc<128; kc+=16) {
            __syncthreads();
            #pragma unroll
            for (int q=0;q<4;q++) {
                int idx = q*128+tid; int r = idx>>5, c4 = idx&31;
                sP[r][c4*4+0]=to_tf32(pre[q].x); sP[r][c4*4+1]=to_tf32(pre[q].y);
                sP[r][c4*4+2]=to_tf32(pre[q].z); sP[r][c4*4+3]=to_tf32(pre[q].w);
            }
            __syncthreads();
            if (kc + 16 < 128) {
                #pragma unroll
                for (int q=0;q<4;q++) {
                    int idx = q*128+tid; int r = idx>>5, c4 = idx&31;
                    pre[q] = *(const float4*)(P + (kc+16+r)*HD + c4*4);
                }
            }
            #pragma unroll
            for (int ks=0; ks<2; ks++) {
                int k0 = kc + ks*8;
                unsigned a[2][4];
                #pragma unroll
                for (int mf=0; mf<2; mf++) {
                    int mr = m_base + mf*16 + qrow;
                    a[mf][0] = __float_as_uint(sA[mr  ][k0+qcol  ]);
                    a[mf][1] = __float_as_uint(sA[mr+8][k0+qcol  ]);
                    a[mf][2] = __float_as_uint(sA[mr  ][k0+qcol+4]);
                    a[mf][3] = __float_as_uint(sA[mr+8][k0+qcol+4]);
                }
                #pragma unroll
                for (int nf=0; nf<8; nf++) {
                    unsigned b0 = __float_as_uint(sP[ks*8+qcol  ][n_base+nf*8+qrow]);
                    unsigned b1 = __float_as_uint(sP[ks*8+qcol+4][n_base+nf*8+qrow]);
                    mma_tf32(acc[nf],   a[0][0],a[0][1],a[0][2],a[0][3], b0,b1);
                    mma_tf32(acc[8+nf], a[1][0],a[1][1],a[1][2],a[1][3], b0,b1);
                }
            }
        }
    };

    // Q: rows j0+d..  with Pq[511-d]
    float accQ[16][4] = {};
    loadA(g_aq, j0 + d);
    gemm(Pq + (size_t)(SEQ-1-d)*HD*HD, accQ);
    __syncthreads();

    // K: rows j0..  with Pk[d]
    float accK[16][4] = {};
    loadA(g_ak, j0);
    gemm(Pk + (size_t)d*HD*HD, accK);

    // dots2[h, j+d, j]: per head (16 cols) dot of Uq,Uk rows.
    // Thread covers cols {2qcol,2qcol+1} of n-frags; head hh uses nf pair (2hh, 2hh+1).
    #pragma unroll
    for (int mf=0; mf<2; mf++) {
        #pragma unroll
        for (int hh=0; hh<4; hh++) {
            int f0 = mf*8 + 2*hh, f1 = f0 + 1;
            float p0 = accQ[f0][0]*accK[f0][0] + accQ[f0][1]*accK[f0][1]
                     + accQ[f1][0]*accK[f1][0] + accQ[f1][1]*accK[f1][1];
            float p1 = accQ[f0][2]*accK[f0][2] + accQ[f0][3]*accK[f0][3]
                     + accQ[f1][2]*accK[f1][2] + accQ[f1][3]*accK[f1][3];
            p0 += __shfl_xor_sync(0xffffffffu, p0, 1);
            p0 += __shfl_xor_sync(0xffffffffu, p0, 2);
            p1 += __shfl_xor_sync(0xffffffffu, p1, 1);
            p1 += __shfl_xor_sync(0xffffffffu, p1, 2);
            if (qcol == 0) {
                int h = (n_base>>4) + hh;
                int r0 = m_base + mf*16 + qrow;
                if (r0 < nvalid) { int j = j0 + r0; g_dots[(size_t)h*SEQ*SEQ + (size_t)(j+d)*SEQ + j] = p0; }
                int r1 = r0 + 8;
                if (r1 < nvalid) { int j = j0 + r1; g_dots[(size_t)h*SEQ*SEQ + (size_t)(j+d)*SEQ + j] = p1; }
            }
        }
    }
    __syncthreads();

    // V: rows j0..  with Pv[d] -> g_uv[d][j][:]
    float accV[16][4] = {};
    loadA(g_av, j0);
    gemm(Pv + (size_t)d*HD*HD, accV);
    #pragma unroll
    for (int mf=0; mf<2; mf++) {
        #pragma unroll
        for (int nf=0; nf<8; nf++) {
            int col = n_base + nf*8 + 2*qcol;
            int r0 = m_base + mf*16 + qrow;
            if (r0 < nvalid)
                *(float2*)(g_uv + ((size_t)d*SEQ + j0 + r0)*HD + col) = make_float2(accV[mf*8+nf][0], accV[mf*8+nf][1]);
            int r1 = r0 + 8;
            if (r1 < nvalid)
                *(float2*)(g_uv + ((size_t)d*SEQ + j0 + r1)*HD + col) = make_float2(accV[mf*8+nf][2], accV[mf*8+nf][3]);
        }
    }
}

// ---------------- dots1 + combine + causal softmax ----------------
__global__ void __launch_bounds__(256) attn_kernel() {
    int h  = blockIdx.y;
    int i0 = blockIdx.x * 16;
    __shared__ float sQ[16][68];
    __shared__ float sK[32][68];
    __shared__ float sD[16][512];
    int tid = threadIdx.x;
    {   int r = tid>>4, c4 = tid&15;
        *(float4*)&sQ[r][c4*4] = *(const float4*)(g_qkv + (i0+r)*1536 + h*64 + c4*4); }
    int r2 = tid>>4, jj = tid&15;
    for (int jc = 0; jc < 512; jc += 32) {
        __syncthreads();
        #pragma unroll
        for (int q=0; q<2; q++) {
            int idx = q*256 + tid; int r = idx>>4, c4 = idx&15;
            *(float4*)&sK[r][c4*4] = *(const float4*)(g_qkv + (jc+r)*1536 + 512 + h*64 + c4*4);
        }
        __syncthreads();
        float a0 = 0.f, a1 = 0.f;
        #pragma unroll
        for (int c=0; c<64; c++) {
            float qv = sQ[r2][c];
            a0 += qv * sK[jj][c];
            a1 += qv * sK[jj+16][c];
        }
        sD[r2][jc+jj]    = a0;
        sD[r2][jc+jj+16] = a1;
    }
    __syncthreads();
    int w = tid>>5, lane = tid&31;
    for (int rr = 2*w; rr < 2*w+2; rr++) {
        int i = i0 + rr;
        float vals[16];
        float m = -1e30f;
        #pragma unroll
        for (int t=0; t<16; t++) {
            int j = lane + t*32;
            float dv = -1e30f;
            if (j <= i)
                dv = 0.0625f * (sD[rr][j] + g_dots[(size_t)h*SEQ*SEQ + (size_t)i*SEQ + j]);
            vals[t] = dv;
            m = fmaxf(m, dv);
        }
        #pragma unroll
        for (int o=16;o;o>>=1) m = fmaxf(m, __shfl_xor_sync(0xffffffffu, m, o));
        float s = 0.f;
        #pragma unroll
        for (int t=0; t<16; t++) {
            float e = (vals[t] > -1e29f) ? __expf(vals[t]-m) : 0.f;
            vals[t] = e; s += e;
        }
        #pragma unroll
        for (int o=16;o;o>>=1) s += __shfl_xor_sync(0xffffffffu, s, o);
        float inv = 1.f / s;
        #pragma unroll
        for (int t=0; t<16; t++) {
            int j = lane + t*32;
            g_dots[(size_t)h*SEQ*SEQ + (size_t)i*SEQ + j] = vals[t]*inv;
        }
    }
}

// ---------------- out1 = attn @ v1 ----------------
__global__ void __launch_bounds__(256) out1_kernel() {
    int h = blockIdx.y, i0 = blockIdx.x*32;
    __shared__ float sAt[32][36];
    __shared__ float sV[32][68];
    int tid = threadIdx.x, ty = tid>>4, tx = tid&15;
    float acc[2][4] = {};
    for (int jc = 0; jc < 512; jc += 32) {
        __syncthreads();
        {   int r = tid>>3, c4 = tid&7;
            *(float4*)&sAt[r][c4*4] = *(const float4*)(g_dots + (size_t)h*SEQ*SEQ + (size_t)(i0+r)*512 + jc + c4*4); }
        #pragma unroll
        for (int q=0; q<2; q++) {
            int idx = q*256 + tid; int r = idx>>4, c4 = idx&15;
            *(float4*)&sV[r][c4*4] = *(const float4*)(g_qkv + (jc+r)*1536 + 1024 + h*64 + c4*4);
        }
        __syncthreads();
        #pragma unroll
        for (int k=0; k<32; k++) {
            float a0 = sAt[ty][k], a1 = sAt[ty+16][k];
            float4 v4 = *(float4*)&sV[k][tx*4];
            acc[0][0]+=a0*v4.x; acc[0][1]+=a0*v4.y; acc[0][2]+=a0*v4.z; acc[0][3]+=a0*v4.w;
            acc[1][0]+=a1*v4.x; acc[1][1]+=a1*v4.y; acc[1][2]+=a1*v4.z; acc[1][3]+=a1*v4.w;
        }
    }
    *(float4*)(g_out1 + (i0+ty)*512    + h*64 + tx*4) = make_float4(acc[0][0],acc[0][1],acc[0][2],acc[0][3]);
    *(float4*)(g_out1 + (i0+ty+16)*512 + h*64 + tx*4) = make_float4(acc[1][0],acc[1][1],acc[1][2],acc[1][3]);
}

// ---------------- out2[i,c] = sum_{j<=i} attn[h(c),i,j] * Uv[i-j][j][c] ----------------
__global__ void __launch_bounds__(512) out2_kernel() {
    int i = blockIdx.x;
    int tid = threadIdx.x;
    int c = tid & 127;
    int part = tid >> 7;
    int h = c >> 4;
    const float* arow = g_dots + (size_t)h*SEQ*SEQ + (size_t)i*SEQ;
    int len = i + 1;
    int chunk = (len + 3) >> 2;
    int jb = part*chunk, je = min(len, jb + chunk);
    float a0=0.f, a1=0.f, a2=0.f, a3=0.f;
    int j = jb;
    for (; j+4 <= je; j += 4) {
        a0 += arow[j]   * g_uv[((size_t)(i-j  )*SEQ + j  )*HD + c];
        a1 += arow[j+1] * g_uv[((size_t)(i-j-1)*SEQ + j+1)*HD + c];
        a2 += arow[j+2] * g_uv[((size_t)(i-j-2)*SEQ + j+2)*HD + c];
        a3 += arow[j+3] * g_uv[((size_t)(i-j-3)*SEQ + j+3)*HD + c];
    }
    for (; j < je; j++)
        a0 += arow[j] * g_uv[((size_t)(i-j)*SEQ + j)*HD + c];
    __shared__ float red[512];
    red[tid] = (a0+a1) + (a2+a3);
    __syncthreads();
    if (part == 0)
        g_out2[i*HD + c] = (red[c] + red[c+128]) + (red[c+256] + red[c+384]);
}

// ---------------- launch ----------------
extern "C" void kernel_launch(void* const* d_in, const int* in_sizes, int n_in,
                              void* d_out, int out_size) {
    const float* x     = (const float*)d_in[0];
    const float* ln_w  = (const float*)d_in[1];
    const float* ln_b  = (const float*)d_in[2];
    const float* w_qkv = (const float*)d_in[3];
    const float* w_q1  = (const float*)d_in[4];
    const float* p_q2  = (const float*)d_in[5];
    const float* w_k1  = (const float*)d_in[6];
    const float* p_k2  = (const float*)d_in[7];
    const float* w_v1  = (const float*)d_in[8];
    const float* p_v2  = (const float*)d_in[9];
    const float* w_v3  = (const float*)d_in[10];
    const float* w_out = (const float*)d_in[11];
    const float* b_out = (const float*)d_in[12];
    float* out = (float*)d_out;

    float *p_xn, *p_qkvb, *p_aq, *p_ak, *p_av, *p_out1b, *p_out2b, *p_tmpb;
    cudaGetSymbolAddress((void**)&p_xn,   g_xn);
    cudaGetSymbolAddress((void**)&p_qkvb, g_qkv);
    cudaGetSymbolAddress((void**)&p_aq,   g_aq);
    cudaGetSymbolAddress((void**)&p_ak,   g_ak);
    cudaGetSymbolAddress((void**)&p_av,   g_av);
    cudaGetSymbolAddress((void**)&p_out1b,g_out1);
    cudaGetSymbolAddress((void**)&p_out2b,g_out2);
    cudaGetSymbolAddress((void**)&p_tmpb, g_tmp);

    ln_kernel<<<512, 256>>>(x, ln_w, ln_b);

    // qkv = xn @ w_qkv  (512x1536x512)
    mma_gemm<0><<<dim3(24,8), 256>>>(p_xn, w_qkv, p_qkvb, 1536, 512, nullptr);
    // aq/ak/av = xn @ {w_q1,w_k1,w_v1}  (512x128x512, fused)
    mma_gemm3<<<dim3(2,8,3), 256>>>(p_xn, w_q1, w_k1, w_v1, p_aq, p_ak, p_av, 128, 512);

    diag_mma<<<dim3(8,512), 128>>>(p_q2, p_k2, p_v2);

    attn_kernel<<<dim3(32,8), 256>>>();
    out1_kernel<<<dim3(16,8), 256>>>();
    out2_kernel<<<512, 512>>>();

    // tmp = (out1 + out2 @ w_v3) * 0.5   (512x512x128)
    mma_gemm<1><<<dim3(8,8), 256>>>(p_out2b, w_v3, p_tmpb, 512, 128, p_out1b);
    // out = tmp @ w_out + b_out          (512x512x512)
    mma_gemm<2><<<dim3(8,8), 256>>>(p_tmpb, w_out, out, 512, 512, b_out);
}